// round 14
// baseline (speedup 1.0000x reference)
#include <cuda_runtime.h>
#include <cuda_bf16.h>

// Problem constants
#define NGROUPS 8
#define CIN 4
#define COUT 4
#define KSIZE 5
#define NPART 8
#define B_    8
#define H_    256
#define W_    512
#define CI_   32
#define CO_   32
#define HP_   32      // H_/NPART rows per slab

// Tile config: 64 cols x 4 rows x 32 co per block.
// NEW mapping: warp w handles cols [8w, 8w+8) (warp-uniform column range ->
// broadcast LDS + warp-level boundary skip). Within a warp:
//   lane = (band: 2 rows) x (cop: 16 co-pairs)
#define TX 64
#define TY 4
#define XS 8
#define NTHREADS 256

#define NTAPS 13
#define SIN_ROWS 6            // TY + 2
#define SIN_COLS 68           // TX + 4
#define SIN_ELEMS (CI_ * SIN_ROWS * SIN_COLS)       // 13056
#define SMEM_BYTES (SIN_ELEMS * 4)                  // 52224 -> 3 blocks/SM

// Masked-weight scratch in global: layout [ci][co][16] (taps padded 13->16)
#define WROW 16
__device__ float g_w[CI_ * CO_ * WROW];

// ---------------------------------------------------------------------------
// Prep: apply PixelCNN group mask (HIDDEN: center visible iff gin<=gout),
// reorder weights to [ci][co][16taps].
// tap 0..9 -> ky=tap/5, kx=tap%5 ; tap 10,11 -> ky=2,kx=0,1 ; tap 12 -> center
// ---------------------------------------------------------------------------
__global__ void prep_weights(const float* __restrict__ w) {
    int i = blockIdx.x * blockDim.x + threadIdx.x;
    if (i >= CI_ * CO_ * WROW) return;
    int k  = i & 15;
    int co = (i >> 4) & 31;
    int ci = i >> 9;
    float val = 0.0f;
    if (k < NTAPS) {
        int ky, kx;
        float m = 1.0f;
        if (k < 10)      { ky = k / 5; kx = k % 5; }
        else if (k == 10){ ky = 2; kx = 0; }
        else if (k == 11){ ky = 2; kx = 1; }
        else             { ky = 2; kx = 2; m = ((ci >> 2) <= (co >> 2)) ? 1.0f : 0.0f; }
        val = w[((co * CI_ + ci) * KSIZE + ky) * KSIZE + kx] * m;
    }
    g_w[i] = val;
}

__device__ __forceinline__ void load_w(float* wgt, const float* __restrict__ wp) {
    const float4* q = (const float4*)wp;
    float4 a = __ldg(q);
    float4 b = __ldg(q + 1);
    float4 c = __ldg(q + 2);
    wgt[0]=a.x; wgt[1]=a.y; wgt[2]=a.z;  wgt[3]=a.w;
    wgt[4]=b.x; wgt[5]=b.y; wgt[6]=b.z;  wgt[7]=b.w;
    wgt[8]=c.x; wgt[9]=c.y; wgt[10]=c.z; wgt[11]=c.w;
    wgt[12] = __ldg(wp + 12);
}

// ---------------------------------------------------------------------------
// Main conv kernel. Grid: (W/TX=8, HP/TY=8, B*NPART=64). Block: 256 threads.
// ---------------------------------------------------------------------------
extern __shared__ float smem[];

__global__ void __launch_bounds__(NTHREADS, 3)
conv_kernel(const float* __restrict__ x,
            const float* __restrict__ bias,
            const float* __restrict__ alpha,
            const int*   __restrict__ widths,
            float* __restrict__ out)
{
    const int tile_x = blockIdx.x;
    const int tile_y = blockIdx.y;
    const int slab   = blockIdx.z;
    const int b      = slab >> 3;
    const int part   = slab & 7;
    const int width  = widths[part];
    const int x0     = tile_x * TX;
    const int y0     = tile_y * TY;          // local row in slab
    const int gy0    = part * HP_ + y0;      // global row

    const int t    = threadIdx.x;
    const int warp = t >> 5;
    const int lane = t & 31;
    // Warp-uniform column range; lane = (band, co-pair)
    const int xsub = warp;                   // 0..7
    const int xoff = xsub * XS;
    const int cop  = lane & 15;
    const int band = lane >> 4;              // 0 or 1
    const int co0  = cop * 2;
    const int r0   = band * 2;               // first out row (local to tile)

    // ---- fast path: whole tile past the valid width -> zeros ----
    if (x0 >= width) {
        const float4 z = make_float4(0.f, 0.f, 0.f, 0.f);
        #pragma unroll
        for (int c = 0; c < 2; ++c)
            #pragma unroll
            for (int o = 0; o < 2; ++o) {
                int base = ((b * CO_ + co0 + c) * H_ + gy0 + r0 + o) * W_ + x0 + xoff;
                *(float4*)(out + base)     = z;
                *(float4*)(out + base + 4) = z;
            }
        return;
    }

    float* sIn = smem;                 // [ci][6][68]

    // ---- stage input tile (masked). Warp w stages ci in [4w, 4w+4). ----
    {
        const int wlim = (width < W_) ? width : W_;
        const int ci0  = warp * 4;
        const float* xb = x + ((size_t)(b * CI_ + ci0) * H_ + part * HP_) * W_;
        float* sb = sIn + ci0 * (SIN_ROWS * SIN_COLS);
        #pragma unroll
        for (int rr = 0; rr < 24; ++rr) {
            const int cio = rr / 6;          // compile-time
            const int r   = rr % 6;          // compile-time
            const int ly  = y0 - 2 + r;      // local row in slab
            const float* grow = xb + (size_t)cio * H_ * W_ + ly * W_;
            float* srow = sb + (cio * SIN_ROWS + r) * SIN_COLS;
            const bool rowok = (ly >= 0) && (ly < HP_);
            int g0 = x0 - 2 + lane;
            int g1 = g0 + 32;
            float v0 = 0.f, v1 = 0.f;
            if (rowok) {
                if (g0 >= 0 && g0 < wlim) v0 = grow[g0];
                if (g1 < wlim)            v1 = grow[g1];
            }
            srow[lane]      = v0;
            srow[lane + 32] = v1;
            if (lane < 4) {
                int g2 = g0 + 64;
                float v2 = (rowok && g2 < wlim) ? grow[g2] : 0.f;
                srow[lane + 64] = v2;
            }
        }
    }
    __syncthreads();

    // acc[co][row][col]
    float acc[2][2][XS];
    #pragma unroll
    for (int c = 0; c < 2; ++c)
        #pragma unroll
        for (int o = 0; o < 2; ++o)
            #pragma unroll
            for (int j = 0; j < XS; ++j) acc[c][o][j] = 0.f;

    // Warp-level boundary skip: warps whose entire 8-col span is beyond the
    // valid width produce all-zero outputs (epilogue masks to 0 anyway).
    const bool live = (x0 + xoff) < width;

    if (live) {
        // Thread reads smem rows r0 .. r0+3 (2 broadcast addr groups per LDS)
        const float* rbase = sIn + r0 * SIN_COLS + xoff;

        // Lockstep ci order; unroll 2 overlaps loop-head loads with FMA tail.
        #pragma unroll 2
        for (int ci = 0; ci < CI_; ++ci) {
            float w0[NTAPS], w1[NTAPS];
            const float* wp = g_w + (ci * CO_ + co0) * WROW;
            load_w(w0, wp);
            load_w(w1, wp + WROW);

            const float* rb = rbase + ci * (SIN_ROWS * SIN_COLS);
            #pragma unroll
            for (int q = 0; q < 4; ++q) {
                float v[12];
                const float4 a0 = *(const float4*)(rb + q * SIN_COLS);
                const float4 a1 = *(const float4*)(rb + q * SIN_COLS + 4);
                const float4 a2 = *(const float4*)(rb + q * SIN_COLS + 8);
                v[0]=a0.x; v[1]=a0.y; v[2]=a0.z; v[3]=a0.w;
                v[4]=a1.x; v[5]=a1.y; v[6]=a1.z; v[7]=a1.w;
                v[8]=a2.x; v[9]=a2.y; v[10]=a2.z; v[11]=a2.w;

                // out row 0 (local r0): ky = q, valid for q = 0,1,2
                if (q < 3) {
                    const int nkx = (q == 2) ? 3 : 5;
                    const int wb  = 5 * q;      // ky0->0, ky1->5, ky2->10
                    #pragma unroll
                    for (int kx = 0; kx < 5; ++kx) {
                        if (kx < nkx) {
                            #pragma unroll
                            for (int j = 0; j < XS; ++j) {
                                acc[0][0][j] = fmaf(v[j + kx], w0[wb + kx], acc[0][0][j]);
                                acc[1][0][j] = fmaf(v[j + kx], w1[wb + kx], acc[1][0][j]);
                            }
                        }
                    }
                }
                // out row 1 (local r0+1): ky = q-1, valid for q = 1,2,3
                if (q >= 1) {
                    const int ky  = q - 1;
                    const int nkx = (ky == 2) ? 3 : 5;
                    const int wb  = 5 * ky;
                    #pragma unroll
                    for (int kx = 0; kx < 5; ++kx) {
                        if (kx < nkx) {
                            #pragma unroll
                            for (int j = 0; j < XS; ++j) {
                                acc[0][1][j] = fmaf(v[j + kx], w0[wb + kx], acc[0][1][j]);
                                acc[1][1][j] = fmaf(v[j + kx], w1[wb + kx], acc[1][1][j]);
                            }
                        }
                    }
                }
            }
        }
    }

    // ---- epilogue: bias, leaky-ReLU, width mask, store ----
    #pragma unroll
    for (int c = 0; c < 2; ++c) {
        const float bz = __ldg(bias  + co0 + c);
        const float al = __ldg(alpha + co0 + c);
        #pragma unroll
        for (int o = 0; o < 2; ++o) {
            float vals[XS];
            #pragma unroll
            for (int j = 0; j < XS; ++j) {
                float y = acc[c][o][j] + bz;
                y = (y > 0.f) ? y : al * y;
                int gx = x0 + xoff + j;
                vals[j] = (gx < width) ? y : 0.f;
            }
            int base = ((b * CO_ + co0 + c) * H_ + gy0 + r0 + o) * W_ + x0 + xoff;
            *(float4*)(out + base)     = make_float4(vals[0], vals[1], vals[2], vals[3]);
            *(float4*)(out + base + 4) = make_float4(vals[4], vals[5], vals[6], vals[7]);
        }
    }
}

// ---------------------------------------------------------------------------
// Launch
// ---------------------------------------------------------------------------
extern "C" void kernel_launch(void* const* d_in, const int* in_sizes, int n_in,
                              void* d_out, int out_size)
{
    const float* x      = (const float*)d_in[0];
    const float* weight = (const float*)d_in[1];
    const float* bias   = (const float*)d_in[2];
    const float* alpha  = (const float*)d_in[3];
    const int*   widths = (const int*)  d_in[4];
    float* out = (float*)d_out;

    (void)in_sizes; (void)n_in; (void)out_size;

    cudaFuncSetAttribute(conv_kernel,
                         cudaFuncAttributeMaxDynamicSharedMemorySize,
                         SMEM_BYTES);

    prep_weights<<<(CI_ * CO_ * WROW + 255) / 256, 256>>>(weight);

    dim3 grid(W_ / TX, HP_ / TY, B_ * NPART);
    conv_kernel<<<grid, NTHREADS, SMEM_BYTES>>>(x, bias, alpha, widths, out);
}

// round 16
// speedup vs baseline: 1.9971x; 1.9971x over previous
#include <cuda_runtime.h>
#include <mma.h>
#include <cstdint>

using namespace nvcuda;

// Problem constants
#define NPART 8
#define B_    8
#define H_    256
#define W_    512
#define CI_   32
#define CO_   32
#define HP_   32
#define NTAPS 13

#define THREADS 256
#define TCOLS   64            // output cols per block
#define TROWS   2             // output rows per block
#define XT_ROWS 4             // staged input rows (y0-2 .. y0+1)
#define XT_COLS 68            // staged cols (x0-2 .. x0+65)
#define XT_STRIDE 36          // floats per (row,col) pixel: 32 ci + pad (144B, 16B-mult)

#define SMEM_FLOATS (XT_ROWS * XT_COLS * XT_STRIDE)   // 9792
#define SMEM_BYTES  (SMEM_FLOATS * 4)                 // 39168 -> 5 blocks/SM

// Masked weights, tf32-rounded, layout [tap][kchunk(4)][k(8)][co(32)]
__device__ float g_wB[NTAPS * 4 * 8 * CO_];

// ---------------------------------------------------------------------------
// Prep: PixelCNN group mask (HIDDEN: center visible iff gin<=gout), tf32 round.
// tap: 0-4 = (ky0,kx0-4), 5-9 = (ky1,kx0-4), 10-12 = (ky2,kx0-2; kx2 gated)
// ---------------------------------------------------------------------------
__global__ void prep_weights(const float* __restrict__ w) {
    int i = blockIdx.x * blockDim.x + threadIdx.x;
    if (i >= NTAPS * 4 * 8 * CO_) return;
    int co  = i & 31;
    int k   = (i >> 5) & 7;
    int kc  = (i >> 8) & 3;
    int tap = i >> 10;
    int ci  = kc * 8 + k;
    int ky  = (tap < 5) ? 0 : (tap < 10 ? 1 : 2);
    int kx  = tap - (ky == 0 ? 0 : (ky == 1 ? 5 : 10));
    float m = 1.0f;
    if (ky == 2 && kx == 2)
        m = ((ci >> 2) <= (co >> 2)) ? 1.0f : 0.0f;
    float val = w[((co * CI_ + ci) * 5 + ky) * 5 + kx] * m;
    g_wB[i] = wmma::__float_to_tf32(val);
}

// ---------------------------------------------------------------------------
// Main kernel. Grid: (W/64=8, H/2=128, B=8). Block: 256 threads (8 warps).
// Warp tile: 16 output cols x 16 co, 2 output rows (2 accumulators).
// ---------------------------------------------------------------------------
extern __shared__ float sX[];   // [4][68][36] input (tf32-rounded), reused as scratch

__global__ void __launch_bounds__(THREADS)
conv_kernel(const float* __restrict__ x,
            const float* __restrict__ bias,
            const float* __restrict__ alpha,
            const int*   __restrict__ widths,
            float* __restrict__ out)
{
    const int x0    = blockIdx.x * TCOLS;
    const int y0    = blockIdx.y * TROWS;
    const int b     = blockIdx.z;
    const int part  = y0 >> 5;
    const int width = widths[part];

    const int tid  = threadIdx.x;
    const int warp = tid >> 5;
    const int lane = tid & 31;

    // ---- fast path: whole tile beyond valid width -> zeros ----
    if (x0 >= width) {
        #pragma unroll
        for (int e = tid; e < TROWS * TCOLS * CO_; e += THREADS) {
            int col = e & 63;
            int row = (e >> 6) & 1;
            int co  = e >> 7;
            out[((size_t)(b * CO_ + co) * H_ + y0 + row) * W_ + x0 + col] = 0.f;
        }
        return;
    }

    // ---- stage input tile (masked, tf32-rounded, coalesced reads) ----
    {
        const int wlim = (width < W_) ? width : W_;
        const int ysl  = part * HP_;
        const int ylb  = (y0 & 31) - 2;
        #pragma unroll
        for (int p = warp; p < XT_ROWS * CI_; p += 8) {
            const int irow = p >> 5;             // 0..3
            const int ci   = p & 31;
            const int ly   = ylb + irow;
            const bool rowok = (ly >= 0) && (ly < HP_);
            const float* grow = x + ((size_t)(b * CI_ + ci) * H_ + (ysl + ly)) * W_;
            // cols: lane, lane+32, and lanes 0..3 -> 64..67
            int g0 = x0 - 2 + lane;
            int g1 = g0 + 32;
            float v0 = 0.f, v1 = 0.f;
            if (rowok) {
                if (g0 >= 0 && g0 < wlim) v0 = wmma::__float_to_tf32(grow[g0]);
                if (g1 < wlim)            v1 = wmma::__float_to_tf32(grow[g1]);
            }
            sX[(irow * XT_COLS + lane)      * XT_STRIDE + ci] = v0;
            sX[(irow * XT_COLS + lane + 32) * XT_STRIDE + ci] = v1;
            if (lane < 4) {
                int g2 = g0 + 64;
                float v2 = (rowok && g2 < wlim) ? wmma::__float_to_tf32(grow[g2]) : 0.f;
                sX[(irow * XT_COLS + lane + 64) * XT_STRIDE + ci] = v2;
            }
        }
    }
    __syncthreads();

    // ---- warp tile assignment ----
    const int c0 = (warp >> 1) * 16;     // output col base (0/16/32/48)
    const int h0 = (warp & 1) * 16;      // co base (0/16)

    wmma::fragment<wmma::accumulator, 16, 16, 8, float> acc[2];
    wmma::fill_fragment(acc[0], 0.0f);
    wmma::fill_fragment(acc[1], 0.0f);

    if (x0 + c0 < width) {               // warp-level width skip
        #pragma unroll 1
        for (int tap = 0; tap < NTAPS; ++tap) {
            const int ky = (tap < 5) ? 0 : (tap < 10 ? 1 : 2);
            const int kx = tap - (ky == 0 ? 0 : (ky == 1 ? 5 : 10));
            #pragma unroll
            for (int kc = 0; kc < 4; ++kc) {
                wmma::fragment<wmma::matrix_b, 16, 16, 8,
                               wmma::precision::tf32, wmma::row_major> bf;
                wmma::load_matrix_sync(bf, g_wB + ((tap * 4 + kc) * 8) * CO_ + h0, CO_);
                #pragma unroll
                for (int r = 0; r < 2; ++r) {
                    wmma::fragment<wmma::matrix_a, 16, 16, 8,
                                   wmma::precision::tf32, wmma::row_major> af;
                    const float* ap = sX + ((r + ky) * XT_COLS + (c0 + kx)) * XT_STRIDE
                                         + kc * 8;
                    wmma::load_matrix_sync(af, ap, XT_STRIDE);
                    wmma::mma_sync(acc[r], af, bf, acc[r]);
                }
            }
        }
    }

    // ---- dump accumulators to smem scratch (col-major: [co][pixel+pad]) ----
    __syncthreads();                      // all warps done reading sX
    float* scr = sX;                      // reuse: 32 * 132 = 4224 floats
    #pragma unroll
    for (int r = 0; r < 2; ++r)
        wmma::store_matrix_sync(scr + h0 * 132 + (r * 64 + c0), acc[r], 132,
                                wmma::mem_col_major);
    __syncthreads();

    // ---- epilogue: bias, leaky-ReLU, width mask; coalesced stores ----
    #pragma unroll
    for (int e = tid; e < TROWS * TCOLS * CO_; e += THREADS) {
        int col = e & 63;
        int row = (e >> 6) & 1;
        int co  = e >> 7;
        float v = scr[co * 132 + row * 64 + col];
        float y = v + __ldg(bias + co);
        float a = __ldg(alpha + co);
        y = (y > 0.f) ? y : a * y;
        int gx = x0 + col;
        out[((size_t)(b * CO_ + co) * H_ + y0 + row) * W_ + gx] =
            (gx < width) ? y : 0.f;
    }
}

// ---------------------------------------------------------------------------
// Launch
// ---------------------------------------------------------------------------
extern "C" void kernel_launch(void* const* d_in, const int* in_sizes, int n_in,
                              void* d_out, int out_size)
{
    const float* x      = (const float*)d_in[0];
    const float* weight = (const float*)d_in[1];
    const float* bias   = (const float*)d_in[2];
    const float* alpha  = (const float*)d_in[3];
    const int*   widths = (const int*)  d_in[4];
    float* out = (float*)d_out;

    (void)in_sizes; (void)n_in; (void)out_size;

    cudaFuncSetAttribute(conv_kernel,
                         cudaFuncAttributeMaxDynamicSharedMemorySize,
                         SMEM_BYTES);

    prep_weights<<<(NTAPS * 4 * 8 * CO_ + 255) / 256, 256>>>(weight);

    dim3 grid(W_ / TCOLS, H_ / TROWS, B_);
    conv_kernel<<<grid, THREADS, SMEM_BYTES>>>(x, bias, alpha, widths, out);
}